// round 6
// baseline (speedup 1.0000x reference)
#include <cuda_runtime.h>
#include <cstdint>

// Problem shape (fixed by the reference):
//   x: (S=128, B=512, D=512) float32
//   src_mask: (B=512, S=128) bool -> materialized by harness as int32 (True = padded)
//   out: (B, G=S-1, 2*D) float32
//
// Math: left[b][g][d]  = prefix_{s<=g} x[s][b][d]*valid[b][s]
//       right[b][g][d] = total[b][d] - left[b][g][d]
// => masked cumsum per (b,d) column. Pure HBM streaming: ~400 MB traffic.

namespace {
constexpr int S = 128;
constexpr int B = 512;
constexpr int D = 512;
constexpr int G = S - 1;          // 127
constexpr int TPB = 256;          // threads per block (half of D)
constexpr int BLOCKS_PER_B = D / TPB;  // 2
}

__global__ __launch_bounds__(TPB, 1)
void frag_prefix_kernel(const float* __restrict__ x,
                        const int* __restrict__ mask,   // int32: nonzero = padded
                        float* __restrict__ out)
{
    __shared__ float valid[S];

    const int b = blockIdx.x >> 1;                       // blockIdx / BLOCKS_PER_B
    const int d = ((blockIdx.x & 1) << 8) + threadIdx.x; // (blockIdx % 2) * 256 + tid

    // Stage mask for this batch row: 0.0f for padded, 1.0f for valid.
    if (threadIdx.x < S) {
        valid[threadIdx.x] = (mask[b * S + threadIdx.x] != 0) ? 0.0f : 1.0f;
    }
    __syncthreads();

    // Load the (b,d) column across s, masking and building the prefix in-place.
    // x index: s*B*D + b*D + d  -> stride B*D between s; coalesced across d.
    const float* __restrict__ xp = x + (size_t)b * D + d;
    float pref[S];
    float p = 0.0f;
    #pragma unroll
    for (int s = 0; s < S; ++s) {
        p += xp[(size_t)s * (B * D)] * valid[s];
        pref[s] = p;
    }
    const float tot = p;  // == pref[S-1]

    // Write left = pref[g], right = tot - pref[g].
    // out index: b*G*2D + g*2D + d (left), +D (right).
    // Streaming stores: output is write-once, keep it out of L2.
    float* __restrict__ op = out + (size_t)b * G * (2 * D) + d;
    #pragma unroll
    for (int g = 0; g < G; ++g) {
        __stcs(op,     pref[g]);
        __stcs(op + D, tot - pref[g]);
        op += 2 * D;
    }
}

extern "C" void kernel_launch(void* const* d_in, const int* in_sizes, int n_in,
                              void* d_out, int out_size)
{
    const float* x    = (const float*)d_in[0];
    const int*   mask = (const int*)d_in[1];
    float*       out  = (float*)d_out;

    frag_prefix_kernel<<<B * BLOCKS_PER_B, TPB>>>(x, mask, out);
}